// round 8
// baseline (speedup 1.0000x reference)
#include <cuda_runtime.h>
#include <cstdint>

#define BB 512
#define TT 2000
#define HH 50
#define CH 32
#define HSTRIDE 68                 // floats per hist row (rows 16B aligned)
#define HIST_FLOATS (33 * HSTRIDE) // 2244 floats = 8976 B per batch slot
#define WPC 2                      // warps per CTA

typedef unsigned long long ull;

__device__ __forceinline__ ull packf2(float a, float b) {
    ull r;
    asm("mov.b64 %0, {%1, %2};" : "=l"(r) : "f"(a), "f"(b));
    return r;
}
__device__ __forceinline__ void unpackf2(ull v, float& lo, float& hi) {
    asm("mov.b64 {%0, %1}, %2;" : "=f"(lo), "=f"(hi) : "l"(v));
}
#define FMA2(acc, a, b) \
    asm("fma.rn.f32x2 %0, %1, %2, %0;" : "+l"(acc) : "l"(a), "l"(b))
#define ADD2(dst, a, b) \
    asm("add.rn.f32x2 %0, %1, %2;" : "=l"(dst) : "l"(a), "l"(b))
#define CP_ASYNC4(dst_u32, src) \
    asm volatile("cp.async.ca.shared.global [%0], [%1], 4;" :: "r"(dst_u32), "l"(src))
#define CP_COMMIT() asm volatile("cp.async.commit_group;")
#define CP_WAIT0()  asm volatile("cp.async.wait_group 0;")

__global__ __launch_bounds__(64, 1)
void rnn_kernel(const float* __restrict__ x,
                const float* __restrict__ W_ih,
                const float* __restrict__ W_hh,
                const float* __restrict__ b_ih,
                const float* __restrict__ b_hh,
                const float* __restrict__ W_out,
                const float* __restrict__ b_out,
                float* __restrict__ y)
{
    // [warp*2 + ab][row][col] — batch B of a warp sits at +HIST_FLOATS from batch A
    __shared__ __align__(16) float hist[WPC * 2][33][HSTRIDE];   // 35,904 B
    __shared__ __align__(16) float xs[WPC * 2][2][CH][4];        //  4,096 B
    __shared__ ull  wosh[3][25];
    __shared__ float bosh[3];

    const int tid  = threadIdx.x;
    const int warp = tid >> 5;
    const int lane = tid & 31;
    const int bA = (blockIdx.x * WPC + warp) * 2;   // batch A; B = bA+1

    for (int i = tid; i < 75; i += 64) {
        const int d = i / 25, q = i % 25;
        wosh[d][q] = packf2(W_out[d * HH + 2 * q], W_out[d * HH + 2 * q + 1]);
    }
    if (tid < 3) bosh[tid] = b_out[tid];

    const int j0 = lane;
    const int j1 = lane + 32;
    const bool j1v = (j1 < HH);

    // weights shared by both batches
    ull w0[25], w1[25];
#pragma unroll
    for (int q = 0; q < 25; q++) {
        w0[q] = packf2(W_hh[j0 * HH + 2 * q], W_hh[j0 * HH + 2 * q + 1]);
        w1[q] = j1v ? packf2(W_hh[j1 * HH + 2 * q], W_hh[j1 * HH + 2 * q + 1]) : 0ull;
    }
    const float wi0a = W_ih[j0 * 3 + 0], wi0b = W_ih[j0 * 3 + 1], wi0c = W_ih[j0 * 3 + 2];
    const float bias0 = b_ih[j0] + b_hh[j0];
    const float wi1a = j1v ? W_ih[j1 * 3 + 0] : 0.f;
    const float wi1b = j1v ? W_ih[j1 * 3 + 1] : 0.f;
    const float wi1c = j1v ? W_ih[j1 * 3 + 2] : 0.f;
    const float bias1 = j1v ? (b_ih[j1] + b_hh[j1]) : 0.f;

    float* const hA = &hist[warp * 2][0][0];         // B region = hA + HIST_FLOATS
    float* const xsA = &xs[warp * 2][0][0][0];       // B region = +2*CH*4 floats

    hA[lane] = 0.f; hA[lane + 32] = 0.f;
    hA[HIST_FLOATS + lane] = 0.f; hA[HIST_FLOATS + lane + 32] = 0.f;

    const float* __restrict__ xbA = x + (size_t)bA * TT * 3;
    float* __restrict__ ybA = y + (size_t)bA * TT * 3;

    const uint32_t xs_sA = (uint32_t)__cvta_generic_to_shared(xsA);

    // stage x chunk 0 for both batches (3 x 4B cp.async per lane per batch)
#pragma unroll
    for (int e = 0; e < 3; e++) {
        const int gi = lane + e * 32;               // 0..95
        const uint32_t doff = (uint32_t)((gi / 3) * 16 + (gi % 3) * 4);
        CP_ASYNC4(xs_sA + doff, xbA + gi);
        CP_ASYNC4(xs_sA + 2 * CH * 16 + doff, xbA + TT * 3 + gi);
    }
    CP_COMMIT();
    CP_WAIT0();
    __syncthreads();      // wosh/bosh + staged x (outside hot loop)

    int buf = 0;
    for (int base = 0; base < TT; base += CH) {
        const int cnt = min(CH, TT - base);          // 32 or 16

        // prefetch next chunk's x into the other buffer for both batches
        if (base + CH < TT) {
            const int ncnt = min(CH, TT - base - CH);
            const uint32_t dbase = xs_sA + (buf ^ 1) * (CH * 16);
#pragma unroll
            for (int e = 0; e < 3; e++) {
                const int gi = lane + e * 32;
                if (gi < ncnt * 3) {
                    const uint32_t doff = (uint32_t)((gi / 3) * 16 + (gi % 3) * 4);
                    CP_ASYNC4(dbase + doff, xbA + (size_t)(base + CH) * 3 + gi);
                    CP_ASYNC4(dbase + 2 * CH * 16 + doff, xbA + TT * 3 + (size_t)(base + CH) * 3 + gi);
                }
            }
        }
        CP_COMMIT();

        const float* __restrict__ xpA = xsA + buf * (CH * 4);

        // ---- recurrence: two independent batches interleaved, no syncs ----
#pragma unroll 2
        for (int s = 0; s < cnt; s++) {
            const float4 xvA = *reinterpret_cast<const float4*>(xpA + s * 4);
            const float4 xvB = *reinterpret_cast<const float4*>(xpA + 2 * CH * 4 + s * 4);
            const float xhA0 = fmaf(xvA.z, wi0c, fmaf(xvA.y, wi0b, fmaf(xvA.x, wi0a, bias0)));
            const float xhA1 = fmaf(xvA.z, wi1c, fmaf(xvA.y, wi1b, fmaf(xvA.x, wi1a, bias1)));
            const float xhB0 = fmaf(xvB.z, wi0c, fmaf(xvB.y, wi0b, fmaf(xvB.x, wi0a, bias0)));
            const float xhB1 = fmaf(xvB.z, wi1c, fmaf(xvB.y, wi1b, fmaf(xvB.x, wi1a, bias1)));

            const float* hr = hA + s * HSTRIDE;      // batch B at +HIST_FLOATS (const imm)
            ull aA0 = packf2(xhA0, 0.f), aA1 = 0ull;
            ull cA0 = packf2(xhA1, 0.f), cA1 = 0ull;
            ull aB0 = packf2(xhB0, 0.f), aB1 = 0ull;
            ull cB0 = packf2(xhB1, 0.f), cB1 = 0ull;
#pragma unroll
            for (int p = 0; p < 12; p++) {
                const ulonglong2 hvA = *reinterpret_cast<const ulonglong2*>(hr + 4 * p);
                const ulonglong2 hvB = *reinterpret_cast<const ulonglong2*>(hr + HIST_FLOATS + 4 * p);
                FMA2(aA0, hvA.x, w0[2 * p]);
                FMA2(aB0, hvB.x, w0[2 * p]);
                FMA2(cA0, hvA.x, w1[2 * p]);
                FMA2(cB0, hvB.x, w1[2 * p]);
                FMA2(aA1, hvA.y, w0[2 * p + 1]);
                FMA2(aB1, hvB.y, w0[2 * p + 1]);
                FMA2(cA1, hvA.y, w1[2 * p + 1]);
                FMA2(cB1, hvB.y, w1[2 * p + 1]);
            }
            const ull hlA = *reinterpret_cast<const ull*>(hr + 48);
            const ull hlB = *reinterpret_cast<const ull*>(hr + HIST_FLOATS + 48);
            FMA2(aA0, hlA, w0[24]);
            FMA2(aB0, hlB, w0[24]);
            FMA2(cA0, hlA, w1[24]);
            FMA2(cB0, hlB, w1[24]);

            ull sA0, sA1, sB0, sB1;
            ADD2(sA0, aA0, aA1); ADD2(sA1, cA0, cA1);
            ADD2(sB0, aB0, aB1); ADD2(sB1, cB0, cB1);
            float lA0, uA0, lA1, uA1, lB0, uB0, lB1, uB1;
            unpackf2(sA0, lA0, uA0);
            unpackf2(sA1, lA1, uA1);
            unpackf2(sB0, lB0, uB0);
            unpackf2(sB1, lB1, uB1);
            const float hA0 = fmaxf(lA0 + uA0, 0.f);
            const float hA1 = fmaxf(lA1 + uA1, 0.f);
            const float hB0 = fmaxf(lB0 + uB0, 0.f);
            const float hB1 = fmaxf(lB1 + uB1, 0.f);

            float* hw = hA + (s + 1) * HSTRIDE;
            hw[lane] = hA0;
            hw[lane + 32] = hA1;
            hw[HIST_FLOATS + lane] = hB0;
            hw[HIST_FLOATS + lane + 32] = hB1;
        }

        // carry last row -> row 0 (same-warp, in-order smem)
        hA[lane] = hA[cnt * HSTRIDE + lane];
        hA[lane + 32] = hA[cnt * HSTRIDE + lane + 32];
        hA[HIST_FLOATS + lane] = hA[HIST_FLOATS + cnt * HSTRIDE + lane];
        hA[HIST_FLOATS + lane + 32] = hA[HIST_FLOATS + cnt * HSTRIDE + lane + 32];

        // ---- chunk projections: lane s -> timestep base+s (row s+1) ----
        if (lane < cnt) {
#pragma unroll 1
            for (int ab = 0; ab < 2; ab++) {
                const float* pr = hA + ab * HIST_FLOATS + (lane + 1) * HSTRIDE;
                float* yo = ybA + (size_t)ab * TT * 3 + (size_t)(base + lane) * 3;
                ull a0 = 0ull, c0 = 0ull, a1 = 0ull, c1 = 0ull, a2 = 0ull, c2 = 0ull;
#pragma unroll
                for (int p = 0; p < 12; p++) {
                    const ulonglong2 hv = *reinterpret_cast<const ulonglong2*>(pr + 4 * p);
                    FMA2(a0, hv.x, wosh[0][2 * p]); FMA2(c0, hv.y, wosh[0][2 * p + 1]);
                    FMA2(a1, hv.x, wosh[1][2 * p]); FMA2(c1, hv.y, wosh[1][2 * p + 1]);
                    FMA2(a2, hv.x, wosh[2][2 * p]); FMA2(c2, hv.y, wosh[2][2 * p + 1]);
                }
                const ull hl = *reinterpret_cast<const ull*>(pr + 48);
                FMA2(a0, hl, wosh[0][24]);
                FMA2(a1, hl, wosh[1][24]);
                FMA2(a2, hl, wosh[2][24]);

                ull s0, s1, s2;
                ADD2(s0, a0, c0); ADD2(s1, a1, c1); ADD2(s2, a2, c2);
                float p0l, p0h, p1l, p1h, p2l, p2h;
                unpackf2(s0, p0l, p0h);
                unpackf2(s1, p1l, p1h);
                unpackf2(s2, p2l, p2h);
                yo[0] = p0l + p0h + bosh[0];
                yo[1] = p1l + p1h + bosh[1];
                yo[2] = p2l + p2h + bosh[2];
            }
        }

        CP_WAIT0();
        __syncwarp();
        buf ^= 1;
    }
}

extern "C" void kernel_launch(void* const* d_in, const int* in_sizes, int n_in,
                              void* d_out, int out_size) {
    const float* x     = (const float*)d_in[0];
    const float* W_ih  = (const float*)d_in[1];
    const float* W_hh  = (const float*)d_in[2];
    const float* b_ih  = (const float*)d_in[3];
    const float* b_hh  = (const float*)d_in[4];
    const float* W_out = (const float*)d_in[5];
    const float* b_out = (const float*)d_in[6];
    float* y = (float*)d_out;

    rnn_kernel<<<BB / (2 * WPC), 64>>>(x, W_ih, W_hh, b_ih, b_hh, W_out, b_out, y);
}

// round 10
// speedup vs baseline: 1.0975x; 1.0975x over previous
#include <cuda_runtime.h>
#include <cstdint>

#define BB 512
#define TT 2000
#define HH 50
#define CH 32
#define HSTRIDE 68                    // floats per hist row
#define ROWB (HSTRIDE * 4)            // 272 bytes per row
#define HIST_FLOATS (33 * HSTRIDE)
#define HIST_B (HIST_FLOATS * 4)      // 8976 bytes per batch slot
#define XSLOT_B 1024                  // x bytes per batch slot (2 bufs x 32 x 16B)
#define WPC 2                         // warps per CTA

typedef unsigned long long ull;

__device__ __forceinline__ ull packf2(float a, float b) {
    ull r;
    asm("mov.b64 %0, {%1, %2};" : "=l"(r) : "f"(a), "f"(b));
    return r;
}
__device__ __forceinline__ void unpackf2(ull v, float& lo, float& hi) {
    asm("mov.b64 {%0, %1}, %2;" : "=f"(lo), "=f"(hi) : "l"(v));
}
#define FMA2(acc, a, b) \
    asm("fma.rn.f32x2 %0, %1, %2, %0;" : "+l"(acc) : "l"(a), "l"(b))
#define ADD2(dst, a, b) \
    asm("add.rn.f32x2 %0, %1, %2;" : "=l"(dst) : "l"(a), "l"(b))

__device__ __forceinline__ void lds2u64(ull& a, ull& b, uint32_t addr) {
    asm volatile("ld.shared.v2.u64 {%0, %1}, [%2];" : "=l"(a), "=l"(b) : "r"(addr));
}
__device__ __forceinline__ ull lds1u64(uint32_t addr) {
    ull a;
    asm volatile("ld.shared.u64 %0, [%1];" : "=l"(a) : "r"(addr));
    return a;
}
__device__ __forceinline__ float4 lds4f32(uint32_t addr) {
    float4 v;
    asm volatile("ld.shared.v4.f32 {%0, %1, %2, %3}, [%4];"
                 : "=f"(v.x), "=f"(v.y), "=f"(v.z), "=f"(v.w) : "r"(addr));
    return v;
}
__device__ __forceinline__ float lds1f32(uint32_t addr) {
    float v;
    asm volatile("ld.shared.f32 %0, [%1];" : "=f"(v) : "r"(addr));
    return v;
}
__device__ __forceinline__ void sts1f32(uint32_t addr, float v) {
    asm volatile("st.shared.f32 [%0], %1;" :: "r"(addr), "f"(v));
}
#define CP_ASYNC4(dst_u32, src) \
    asm volatile("cp.async.ca.shared.global [%0], [%1], 4;" :: "r"(dst_u32), "l"(src))
#define CP_COMMIT() asm volatile("cp.async.commit_group;")
#define CP_WAIT0()  asm volatile("cp.async.wait_group 0;")

__global__ __maxnreg__(200)
void rnn_kernel(const float* __restrict__ x,
                const float* __restrict__ W_ih,
                const float* __restrict__ W_hh,
                const float* __restrict__ b_ih,
                const float* __restrict__ b_hh,
                const float* __restrict__ W_out,
                const float* __restrict__ b_out,
                float* __restrict__ y)
{
    __shared__ __align__(16) float hist[WPC * 2][33][HSTRIDE];   // 35,904 B
    __shared__ __align__(16) float xs[WPC * 2][2][CH][4];        //  4,096 B
    __shared__ ull  wosh[3][25];
    __shared__ float bosh[3];

    const int tid  = threadIdx.x;
    const int warp = tid >> 5;
    const int lane = tid & 31;
    const int bA = (blockIdx.x * WPC + warp) * 2;

    for (int i = tid; i < 75; i += 64) {
        const int d = i / 25, q = i % 25;
        wosh[d][q] = packf2(W_out[d * HH + 2 * q], W_out[d * HH + 2 * q + 1]);
    }
    if (tid < 3) bosh[tid] = b_out[tid];

    const int j0 = lane;
    const int j1 = lane + 32;
    const bool j1v = (j1 < HH);

    ull w0[25], w1[25];
#pragma unroll
    for (int q = 0; q < 25; q++) {
        w0[q] = packf2(W_hh[j0 * HH + 2 * q], W_hh[j0 * HH + 2 * q + 1]);
        w1[q] = j1v ? packf2(W_hh[j1 * HH + 2 * q], W_hh[j1 * HH + 2 * q + 1]) : 0ull;
    }
    const float wi0a = W_ih[j0 * 3 + 0], wi0b = W_ih[j0 * 3 + 1], wi0c = W_ih[j0 * 3 + 2];
    const float bias0 = b_ih[j0] + b_hh[j0];
    const float wi1a = j1v ? W_ih[j1 * 3 + 0] : 0.f;
    const float wi1b = j1v ? W_ih[j1 * 3 + 1] : 0.f;
    const float wi1c = j1v ? W_ih[j1 * 3 + 2] : 0.f;
    const float bias1 = j1v ? (b_ih[j1] + b_hh[j1]) : 0.f;

    const int slotA = warp * 2;
    const uint32_t hA_s = (uint32_t)__cvta_generic_to_shared(&hist[slotA][0][0]);
    const uint32_t xs_s = (uint32_t)__cvta_generic_to_shared(&xs[slotA][0][0][0]);
    const uint32_t l4  = lane * 4;
    const uint32_t l4b = l4 + 128;

    // h_{-1} = 0, both batches (cols 50..63 rewritten each step)
    sts1f32(hA_s + l4, 0.f);
    sts1f32(hA_s + l4b, 0.f);
    sts1f32(hA_s + HIST_B + l4, 0.f);
    sts1f32(hA_s + HIST_B + l4b, 0.f);

    const float* __restrict__ xbA = x + (size_t)bA * TT * 3;
    float* __restrict__ ybA = y + (size_t)bA * TT * 3;

    // stage x chunk 0 for both batches
#pragma unroll
    for (int e = 0; e < 3; e++) {
        const int gi = lane + e * 32;
        const uint32_t doff = (uint32_t)((gi / 3) * 16 + (gi % 3) * 4);
        CP_ASYNC4(xs_s + doff, xbA + gi);
        CP_ASYNC4(xs_s + XSLOT_B + doff, xbA + TT * 3 + gi);
    }
    CP_COMMIT();
    CP_WAIT0();
    __syncthreads();

    int buf = 0;
    for (int base = 0; base < TT; base += CH) {
        const int cnt = min(CH, TT - base);        // 32 or 16

        // prefetch next chunk's x
        if (base + CH < TT) {
            const int ncnt = min(CH, TT - base - CH);
            const uint32_t dbase = xs_s + (uint32_t)((buf ^ 1) * 512);
#pragma unroll
            for (int e = 0; e < 3; e++) {
                const int gi = lane + e * 32;
                if (gi < ncnt * 3) {
                    const uint32_t doff = (uint32_t)((gi / 3) * 16 + (gi % 3) * 4);
                    CP_ASYNC4(dbase + doff, xbA + (size_t)(base + CH) * 3 + gi);
                    CP_ASYNC4(dbase + XSLOT_B + doff, xbA + TT * 3 + (size_t)(base + CH) * 3 + gi);
                }
            }
        }
        CP_COMMIT();

        uint32_t xa = xs_s + (uint32_t)(buf * 512);
        uint32_t ha = hA_s;

        // ---- recurrence: 2 independent batches, asm-addressed, no syncs ----
#pragma unroll 1
        for (int s = 0; s < cnt; s++) {
            const float4 xvA = lds4f32(xa);
            const float4 xvB = lds4f32(xa + XSLOT_B);
            xa += 16;
            const float xhA0 = fmaf(xvA.z, wi0c, fmaf(xvA.y, wi0b, fmaf(xvA.x, wi0a, bias0)));
            const float xhA1 = fmaf(xvA.z, wi1c, fmaf(xvA.y, wi1b, fmaf(xvA.x, wi1a, bias1)));
            const float xhB0 = fmaf(xvB.z, wi0c, fmaf(xvB.y, wi0b, fmaf(xvB.x, wi0a, bias0)));
            const float xhB1 = fmaf(xvB.z, wi1c, fmaf(xvB.y, wi1b, fmaf(xvB.x, wi1a, bias1)));

            ull aA0 = packf2(xhA0, 0.f), aA1 = 0ull;
            ull cA0 = packf2(xhA1, 0.f), cA1 = 0ull;
            ull aB0 = packf2(xhB0, 0.f), aB1 = 0ull;
            ull cB0 = packf2(xhB1, 0.f), cB1 = 0ull;
#pragma unroll
            for (int p = 0; p < 12; p++) {
                ull hxA, hyA, hxB, hyB;
                lds2u64(hxA, hyA, ha + (uint32_t)(p * 16));
                lds2u64(hxB, hyB, ha + (uint32_t)(HIST_B + p * 16));
                FMA2(aA0, hxA, w0[2 * p]);
                FMA2(aB0, hxB, w0[2 * p]);
                FMA2(cA0, hxA, w1[2 * p]);
                FMA2(cB0, hxB, w1[2 * p]);
                FMA2(aA1, hyA, w0[2 * p + 1]);
                FMA2(aB1, hyB, w0[2 * p + 1]);
                FMA2(cA1, hyA, w1[2 * p + 1]);
                FMA2(cB1, hyB, w1[2 * p + 1]);
            }
            const ull hlA = lds1u64(ha + 192);
            const ull hlB = lds1u64(ha + HIST_B + 192);
            FMA2(aA0, hlA, w0[24]);
            FMA2(aB0, hlB, w0[24]);
            FMA2(cA0, hlA, w1[24]);
            FMA2(cB0, hlB, w1[24]);

            ull sA0, sA1, sB0, sB1;
            ADD2(sA0, aA0, aA1); ADD2(sA1, cA0, cA1);
            ADD2(sB0, aB0, aB1); ADD2(sB1, cB0, cB1);
            float lA0, uA0, lA1, uA1, lB0, uB0, lB1, uB1;
            unpackf2(sA0, lA0, uA0);
            unpackf2(sA1, lA1, uA1);
            unpackf2(sB0, lB0, uB0);
            unpackf2(sB1, lB1, uB1);

            const uint32_t hw = ha + ROWB;
            sts1f32(hw + l4,  fmaxf(lA0 + uA0, 0.f));
            sts1f32(hw + l4b, fmaxf(lA1 + uA1, 0.f));
            sts1f32(hw + HIST_B + l4,  fmaxf(lB0 + uB0, 0.f));
            sts1f32(hw + HIST_B + l4b, fmaxf(lB1 + uB1, 0.f));
            ha = hw;
        }

        // carry last row -> row 0 (same-warp, in-order MIO)
        {
            const uint32_t src = hA_s + (uint32_t)(cnt * ROWB);
            sts1f32(hA_s + l4,  lds1f32(src + l4));
            sts1f32(hA_s + l4b, lds1f32(src + l4b));
            sts1f32(hA_s + HIST_B + l4,  lds1f32(src + HIST_B + l4));
            sts1f32(hA_s + HIST_B + l4b, lds1f32(src + HIST_B + l4b));
        }

        // ---- chunk projections: lane s -> timestep base+s (row s+1) ----
        if (lane < cnt) {
#pragma unroll 1
            for (int ab = 0; ab < 2; ab++) {
                const uint32_t pr = hA_s + (uint32_t)(ab * HIST_B) + (uint32_t)((lane + 1) * ROWB);
                float* yo = ybA + (size_t)ab * TT * 3 + (size_t)(base + lane) * 3;
                ull a0 = 0ull, c0 = 0ull, a1 = 0ull, c1 = 0ull, a2 = 0ull, c2 = 0ull;
#pragma unroll
                for (int p = 0; p < 12; p++) {
                    ull hx, hy;
                    lds2u64(hx, hy, pr + (uint32_t)(p * 16));
                    FMA2(a0, hx, wosh[0][2 * p]); FMA2(c0, hy, wosh[0][2 * p + 1]);
                    FMA2(a1, hx, wosh[1][2 * p]); FMA2(c1, hy, wosh[1][2 * p + 1]);
                    FMA2(a2, hx, wosh[2][2 * p]); FMA2(c2, hy, wosh[2][2 * p + 1]);
                }
                const ull hl = lds1u64(pr + 192);
                FMA2(a0, hl, wosh[0][24]);
                FMA2(a1, hl, wosh[1][24]);
                FMA2(a2, hl, wosh[2][24]);

                ull s0, s1, s2;
                ADD2(s0, a0, c0); ADD2(s1, a1, c1); ADD2(s2, a2, c2);
                float p0l, p0h, p1l, p1h, p2l, p2h;
                unpackf2(s0, p0l, p0h);
                unpackf2(s1, p1l, p1h);
                unpackf2(s2, p2l, p2h);
                yo[0] = p0l + p0h + bosh[0];
                yo[1] = p1l + p1h + bosh[1];
                yo[2] = p2l + p2h + bosh[2];
            }
        }

        CP_WAIT0();
        __syncwarp();
        buf ^= 1;
    }
}

extern "C" void kernel_launch(void* const* d_in, const int* in_sizes, int n_in,
                              void* d_out, int out_size) {
    const float* x     = (const float*)d_in[0];
    const float* W_ih  = (const float*)d_in[1];
    const float* W_hh  = (const float*)d_in[2];
    const float* b_ih  = (const float*)d_in[3];
    const float* b_hh  = (const float*)d_in[4];
    const float* W_out = (const float*)d_in[5];
    const float* b_out = (const float*)d_in[6];
    float* y = (float*)d_out;

    rnn_kernel<<<BB / (2 * WPC), 64>>>(x, W_ih, W_hh, b_ih, b_hh, W_out, b_out, y);
}

// round 11
// speedup vs baseline: 1.1195x; 1.0201x over previous
#include <cuda_runtime.h>
#include <cstdint>

#define BB 512
#define TT 2000
#define HH 50
#define CH 32
#define HSTRIDE 68                    // floats per hist row
#define ROWB (HSTRIDE * 4)            // 272 bytes per row
#define HIST_FLOATS (33 * HSTRIDE)
#define HIST_B (HIST_FLOATS * 4)      // 8976 bytes per batch slot
#define XSLOT_B 1024                  // x bytes per batch slot
#define WPC 2                         // warps per CTA

typedef unsigned long long ull;

__device__ __forceinline__ ull packf2(float a, float b) {
    ull r;
    asm("mov.b64 %0, {%1, %2};" : "=l"(r) : "f"(a), "f"(b));
    return r;
}
__device__ __forceinline__ void unpackf2(ull v, float& lo, float& hi) {
    asm("mov.b64 {%0, %1}, %2;" : "=f"(lo), "=f"(hi) : "l"(v));
}
#define FMA2(acc, a, b) \
    asm("fma.rn.f32x2 %0, %1, %2, %0;" : "+l"(acc) : "l"(a), "l"(b))
#define ADD2(dst, a, b) \
    asm("add.rn.f32x2 %0, %1, %2;" : "=l"(dst) : "l"(a), "l"(b))

__device__ __forceinline__ void lds2u64(ull& a, ull& b, uint32_t addr) {
    asm volatile("ld.shared.v2.u64 {%0, %1}, [%2];" : "=l"(a), "=l"(b) : "r"(addr));
}
__device__ __forceinline__ ull lds1u64(uint32_t addr) {
    ull a;
    asm volatile("ld.shared.u64 %0, [%1];" : "=l"(a) : "r"(addr));
    return a;
}
__device__ __forceinline__ float4 lds4f32(uint32_t addr) {
    float4 v;
    asm volatile("ld.shared.v4.f32 {%0, %1, %2, %3}, [%4];"
                 : "=f"(v.x), "=f"(v.y), "=f"(v.z), "=f"(v.w) : "r"(addr));
    return v;
}
__device__ __forceinline__ float lds1f32(uint32_t addr) {
    float v;
    asm volatile("ld.shared.f32 %0, [%1];" : "=f"(v) : "r"(addr));
    return v;
}
__device__ __forceinline__ void sts1f32(uint32_t addr, float v) {
    asm volatile("st.shared.f32 [%0], %1;" :: "r"(addr), "f"(v));
}
#define CP_ASYNC4(dst_u32, src) \
    asm volatile("cp.async.ca.shared.global [%0], [%1], 4;" :: "r"(dst_u32), "l"(src))
#define CP_COMMIT() asm volatile("cp.async.commit_group;")
#define CP_WAIT0()  asm volatile("cp.async.wait_group 0;")

__global__ __maxnreg__(240)
void rnn_kernel(const float* __restrict__ x,
                const float* __restrict__ W_ih,
                const float* __restrict__ W_hh,
                const float* __restrict__ b_ih,
                const float* __restrict__ b_hh,
                const float* __restrict__ W_out,
                const float* __restrict__ b_out,
                float* __restrict__ y)
{
    __shared__ __align__(16) float hist[WPC * 2][33][HSTRIDE];   // 35,904 B
    __shared__ __align__(16) float xs[WPC * 2][2][CH][4];        //  4,096 B
    __shared__ ull  wosh[3][25];
    __shared__ float bosh[3];

    const int tid  = threadIdx.x;
    const int warp = tid >> 5;
    const int lane = tid & 31;
    const int bA = (blockIdx.x * WPC + warp) * 2;

    for (int i = tid; i < 75; i += 64) {
        const int d = i / 25, q = i % 25;
        wosh[d][q] = packf2(W_out[d * HH + 2 * q], W_out[d * HH + 2 * q + 1]);
    }
    if (tid < 3) bosh[tid] = b_out[tid];

    const int j0 = lane;
    const int j1 = lane + 32;
    const bool j1v = (j1 < HH);

    ull w0[25], w1[25];
#pragma unroll
    for (int q = 0; q < 25; q++) {
        w0[q] = packf2(W_hh[j0 * HH + 2 * q], W_hh[j0 * HH + 2 * q + 1]);
        w1[q] = j1v ? packf2(W_hh[j1 * HH + 2 * q], W_hh[j1 * HH + 2 * q + 1]) : 0ull;
    }
    const float wi0a = W_ih[j0 * 3 + 0], wi0b = W_ih[j0 * 3 + 1], wi0c = W_ih[j0 * 3 + 2];
    const float bias0 = b_ih[j0] + b_hh[j0];
    const float wi1a = j1v ? W_ih[j1 * 3 + 0] : 0.f;
    const float wi1b = j1v ? W_ih[j1 * 3 + 1] : 0.f;
    const float wi1c = j1v ? W_ih[j1 * 3 + 2] : 0.f;
    const float bias1 = j1v ? (b_ih[j1] + b_hh[j1]) : 0.f;

    const int slotA = warp * 2;
    const uint32_t hA_s = (uint32_t)__cvta_generic_to_shared(&hist[slotA][0][0]);
    const uint32_t xs_s = (uint32_t)__cvta_generic_to_shared(&xs[slotA][0][0][0]);
    const uint32_t l4  = lane * 4;
    const uint32_t l4b = l4 + 128;

    sts1f32(hA_s + l4, 0.f);
    sts1f32(hA_s + l4b, 0.f);
    sts1f32(hA_s + HIST_B + l4, 0.f);
    sts1f32(hA_s + HIST_B + l4b, 0.f);

    const float* __restrict__ xbA = x + (size_t)bA * TT * 3;
    float* __restrict__ ybA = y + (size_t)bA * TT * 3;

    // stage x chunk 0 for both batches
#pragma unroll
    for (int e = 0; e < 3; e++) {
        const int gi = lane + e * 32;
        const uint32_t doff = (uint32_t)((gi / 3) * 16 + (gi % 3) * 4);
        CP_ASYNC4(xs_s + doff, xbA + gi);
        CP_ASYNC4(xs_s + XSLOT_B + doff, xbA + TT * 3 + gi);
    }
    CP_COMMIT();
    CP_WAIT0();
    __syncthreads();

    int buf = 0;
    for (int base = 0; base < TT; base += CH) {
        const int cnt = min(CH, TT - base);

        if (base + CH < TT) {
            const int ncnt = min(CH, TT - base - CH);
            const uint32_t dbase = xs_s + (uint32_t)((buf ^ 1) * 512);
#pragma unroll
            for (int e = 0; e < 3; e++) {
                const int gi = lane + e * 32;
                if (gi < ncnt * 3) {
                    const uint32_t doff = (uint32_t)((gi / 3) * 16 + (gi % 3) * 4);
                    CP_ASYNC4(dbase + doff, xbA + (size_t)(base + CH) * 3 + gi);
                    CP_ASYNC4(dbase + XSLOT_B + doff, xbA + TT * 3 + (size_t)(base + CH) * 3 + gi);
                }
            }
        }
        CP_COMMIT();

        uint32_t xa = xs_s + (uint32_t)(buf * 512);
        uint32_t ha = hA_s;

        // ---- recurrence: 2 batches/warp, front-batched loads (MLP 13) ----
#pragma unroll 1
        for (int s = 0; s < cnt; s++) {
            // x + input projection (off the h critical path)
            const float4 xvA = lds4f32(xa);
            const float4 xvB = lds4f32(xa + XSLOT_B);
            xa += 16;
            const float xhA0 = fmaf(xvA.z, wi0c, fmaf(xvA.y, wi0b, fmaf(xvA.x, wi0a, bias0)));
            const float xhA1 = fmaf(xvA.z, wi1c, fmaf(xvA.y, wi1b, fmaf(xvA.x, wi1a, bias1)));
            const float xhB0 = fmaf(xvB.z, wi0c, fmaf(xvB.y, wi0b, fmaf(xvB.x, wi0a, bias0)));
            const float xhB1 = fmaf(xvB.z, wi1c, fmaf(xvB.y, wi1b, fmaf(xvB.x, wi1a, bias1)));

            // front-batch ALL of A's h loads (13 back-to-back LDS => one 29cyc wait)
            ull hxA[12], hyA[12];
#pragma unroll
            for (int p = 0; p < 12; p++)
                lds2u64(hxA[p], hyA[p], ha + (uint32_t)(p * 16));
            const ull hlA = lds1u64(ha + 192);

            ull aA0 = packf2(xhA0, 0.f), aA1 = 0ull;
            ull cA0 = packf2(xhA1, 0.f), cA1 = 0ull;

            // A's FMAs; B's loads interleaved to fill rt-2 issue gaps
            ull hxB[12], hyB[12];
#pragma unroll
            for (int p = 0; p < 12; p++) {
                lds2u64(hxB[p], hyB[p], ha + (uint32_t)(HIST_B + p * 16));
                FMA2(aA0, hxA[p], w0[2 * p]);
                FMA2(cA0, hxA[p], w1[2 * p]);
                FMA2(aA1, hyA[p], w0[2 * p + 1]);
                FMA2(cA1, hyA[p], w1[2 * p + 1]);
            }
            const ull hlB = lds1u64(ha + HIST_B + 192);
            FMA2(aA0, hlA, w0[24]);
            FMA2(cA0, hlA, w1[24]);

            // A tail + store
            {
                ull sA0, sA1;
                ADD2(sA0, aA0, aA1);
                ADD2(sA1, cA0, cA1);
                float lo0, up0, lo1, up1;
                unpackf2(sA0, lo0, up0);
                unpackf2(sA1, lo1, up1);
                sts1f32(ha + ROWB + l4,  fmaxf(lo0 + up0, 0.f));
                sts1f32(ha + ROWB + l4b, fmaxf(lo1 + up1, 0.f));
            }

            // B's FMAs (loads long complete)
            ull aB0 = packf2(xhB0, 0.f), aB1 = 0ull;
            ull cB0 = packf2(xhB1, 0.f), cB1 = 0ull;
#pragma unroll
            for (int p = 0; p < 12; p++) {
                FMA2(aB0, hxB[p], w0[2 * p]);
                FMA2(cB0, hxB[p], w1[2 * p]);
                FMA2(aB1, hyB[p], w0[2 * p + 1]);
                FMA2(cB1, hyB[p], w1[2 * p + 1]);
            }
            FMA2(aB0, hlB, w0[24]);
            FMA2(cB0, hlB, w1[24]);

            // B tail + store
            {
                ull sB0, sB1;
                ADD2(sB0, aB0, aB1);
                ADD2(sB1, cB0, cB1);
                float lo0, up0, lo1, up1;
                unpackf2(sB0, lo0, up0);
                unpackf2(sB1, lo1, up1);
                sts1f32(ha + ROWB + HIST_B + l4,  fmaxf(lo0 + up0, 0.f));
                sts1f32(ha + ROWB + HIST_B + l4b, fmaxf(lo1 + up1, 0.f));
            }

            ha += ROWB;
        }

        // carry last row -> row 0
        {
            const uint32_t src = hA_s + (uint32_t)(cnt * ROWB);
            sts1f32(hA_s + l4,  lds1f32(src + l4));
            sts1f32(hA_s + l4b, lds1f32(src + l4b));
            sts1f32(hA_s + HIST_B + l4,  lds1f32(src + HIST_B + l4));
            sts1f32(hA_s + HIST_B + l4b, lds1f32(src + HIST_B + l4b));
        }

        // ---- chunk projections: lane s -> timestep base+s (row s+1) ----
        if (lane < cnt) {
#pragma unroll 1
            for (int ab = 0; ab < 2; ab++) {
                const uint32_t pr = hA_s + (uint32_t)(ab * HIST_B) + (uint32_t)((lane + 1) * ROWB);
                float* yo = ybA + (size_t)ab * TT * 3 + (size_t)(base + lane) * 3;
                ull a0 = 0ull, c0 = 0ull, a1 = 0ull, c1 = 0ull, a2 = 0ull, c2 = 0ull;
#pragma unroll
                for (int p = 0; p < 12; p++) {
                    ull hx, hy;
                    lds2u64(hx, hy, pr + (uint32_t)(p * 16));
                    FMA2(a0, hx, wosh[0][2 * p]); FMA2(c0, hy, wosh[0][2 * p + 1]);
                    FMA2(a1, hx, wosh[1][2 * p]); FMA2(c1, hy, wosh[1][2 * p + 1]);
                    FMA2(a2, hx, wosh[2][2 * p]); FMA2(c2, hy, wosh[2][2 * p + 1]);
                }
                const ull hl = lds1u64(pr + 192);
                FMA2(a0, hl, wosh[0][24]);
                FMA2(a1, hl, wosh[1][24]);
                FMA2(a2, hl, wosh[2][24]);

                ull s0, s1, s2;
                ADD2(s0, a0, c0); ADD2(s1, a1, c1); ADD2(s2, a2, c2);
                float p0l, p0h, p1l, p1h, p2l, p2h;
                unpackf2(s0, p0l, p0h);
                unpackf2(s1, p1l, p1h);
                unpackf2(s2, p2l, p2h);
                yo[0] = p0l + p0h + bosh[0];
                yo[1] = p1l + p1h + bosh[1];
                yo[2] = p2l + p2h + bosh[2];
            }
        }

        CP_WAIT0();
        __syncwarp();
        buf ^= 1;
    }
}

extern "C" void kernel_launch(void* const* d_in, const int* in_sizes, int n_in,
                              void* d_out, int out_size) {
    const float* x     = (const float*)d_in[0];
    const float* W_ih  = (const float*)d_in[1];
    const float* W_hh  = (const float*)d_in[2];
    const float* b_ih  = (const float*)d_in[3];
    const float* b_hh  = (const float*)d_in[4];
    const float* W_out = (const float*)d_in[5];
    const float* b_out = (const float*)d_in[6];
    float* y = (float*)d_out;

    rnn_kernel<<<BB / (2 * WPC), 64>>>(x, W_ih, W_hh, b_ih, b_hh, W_out, b_out, y);
}

// round 13
// speedup vs baseline: 2.0191x; 1.8035x over previous
#include <cuda_runtime.h>
#include <cstdint>

#define BB 512
#define TT 2000
#define HH 50
#define CH 32
#define HSTRIDE 68                 // floats per hist row
#define ROWB (HSTRIDE * 4)         // 272 B per row

typedef unsigned long long ull;

__device__ __forceinline__ ull packf2(float a, float b) {
    ull r;
    asm("mov.b64 %0, {%1, %2};" : "=l"(r) : "f"(a), "f"(b));
    return r;
}
__device__ __forceinline__ void unpackf2(ull v, float& lo, float& hi) {
    asm("mov.b64 {%0, %1}, %2;" : "=f"(lo), "=f"(hi) : "l"(v));
}
#define FMA2(acc, a, b) \
    asm("fma.rn.f32x2 %0, %1, %2, %0;" : "+l"(acc) : "l"(a), "l"(b))
#define ADD2(dst, a, b) \
    asm("add.rn.f32x2 %0, %1, %2;" : "=l"(dst) : "l"(a), "l"(b))

// --- immediate-offset shared accessors (no per-access IADD) ---
template<int IMM>
__device__ __forceinline__ void lds2i(ull& a, ull& b, uint32_t base) {
    asm volatile("ld.shared.v2.u64 {%0, %1}, [%2 + %3];"
                 : "=l"(a), "=l"(b) : "r"(base), "n"(IMM));
}
template<int IMM>
__device__ __forceinline__ ull lds1i(uint32_t base) {
    ull a;
    asm volatile("ld.shared.u64 %0, [%1 + %2];" : "=l"(a) : "r"(base), "n"(IMM));
    return a;
}
template<int IMM>
__device__ __forceinline__ float4 lds4i(uint32_t base) {
    float4 v;
    asm volatile("ld.shared.v4.f32 {%0, %1, %2, %3}, [%4 + %5];"
                 : "=f"(v.x), "=f"(v.y), "=f"(v.z), "=f"(v.w) : "r"(base), "n"(IMM));
    return v;
}
template<int IMM>
__device__ __forceinline__ void sts1i(uint32_t base, float v) {
    asm volatile("st.shared.f32 [%0 + %1], %2;" :: "r"(base), "n"(IMM), "f"(v) : "memory");
}
__device__ __forceinline__ float lds1f(uint32_t addr) {
    float v;
    asm volatile("ld.shared.f32 %0, [%1];" : "=f"(v) : "r"(addr));
    return v;
}
__device__ __forceinline__ void sts1f(uint32_t addr, float v) {
    asm volatile("st.shared.f32 [%0], %1;" :: "r"(addr), "f"(v) : "memory");
}
#define CP_ASYNC4(dst_u32, src) \
    asm volatile("cp.async.ca.shared.global [%0], [%1], 4;" :: "r"(dst_u32), "l"(src))
#define CP_COMMIT() asm volatile("cp.async.commit_group;")
#define CP_WAIT0()  asm volatile("cp.async.wait_group 0;")

// one recurrence step, software-pipelined:
//  - P0..P3 hold vectors 0..3 of row U (loaded at end of previous step)
//  - vectors 4..11 + hl loaded in-stream (first use >= 32 cyc after issue)
//  - stores row U+1, then prefetches its vectors 0..3 into P
#define STEP(U) do {                                                          \
    const float4 xv = lds4i<(U) * 16>(xag);                                   \
    ull h4x,h4y,h5x,h5y,h6x,h6y,h7x,h7y,h8x,h8y,h9x,h9y,h10x,h10y,h11x,h11y;  \
    lds2i<(U)*ROWB +  64>(h4x,  h4y,  hag);                                   \
    lds2i<(U)*ROWB +  80>(h5x,  h5y,  hag);                                   \
    lds2i<(U)*ROWB +  96>(h6x,  h6y,  hag);                                   \
    lds2i<(U)*ROWB + 112>(h7x,  h7y,  hag);                                   \
    lds2i<(U)*ROWB + 128>(h8x,  h8y,  hag);                                   \
    lds2i<(U)*ROWB + 144>(h9x,  h9y,  hag);                                   \
    lds2i<(U)*ROWB + 160>(h10x, h10y, hag);                                   \
    lds2i<(U)*ROWB + 176>(h11x, h11y, hag);                                   \
    const ull hl = lds1i<(U)*ROWB + 192>(hag);                                \
    const float xh0 = fmaf(xv.z, wi0c, fmaf(xv.y, wi0b, fmaf(xv.x, wi0a, bias0))); \
    const float xh1 = fmaf(xv.z, wi1c, fmaf(xv.y, wi1b, fmaf(xv.x, wi1a, bias1))); \
    ull a0 = packf2(xh0, 0.f), a1 = 0ull;                                     \
    ull b0 = packf2(xh1, 0.f), b1 = 0ull;                                     \
    FMA2(a0, P0x, w0[0]);  FMA2(b0, P0x, w1[0]);                              \
    FMA2(a1, P0y, w0[1]);  FMA2(b1, P0y, w1[1]);                              \
    FMA2(a0, P1x, w0[2]);  FMA2(b0, P1x, w1[2]);                              \
    FMA2(a1, P1y, w0[3]);  FMA2(b1, P1y, w1[3]);                              \
    FMA2(a0, P2x, w0[4]);  FMA2(b0, P2x, w1[4]);                              \
    FMA2(a1, P2y, w0[5]);  FMA2(b1, P2y, w1[5]);                              \
    FMA2(a0, P3x, w0[6]);  FMA2(b0, P3x, w1[6]);                              \
    FMA2(a1, P3y, w0[7]);  FMA2(b1, P3y, w1[7]);                              \
    FMA2(a0, h4x,  w0[8]);  FMA2(b0, h4x,  w1[8]);                            \
    FMA2(a1, h4y,  w0[9]);  FMA2(b1, h4y,  w1[9]);                            \
    FMA2(a0, h5x,  w0[10]); FMA2(b0, h5x,  w1[10]);                           \
    FMA2(a1, h5y,  w0[11]); FMA2(b1, h5y,  w1[11]);                           \
    FMA2(a0, h6x,  w0[12]); FMA2(b0, h6x,  w1[12]);                           \
    FMA2(a1, h6y,  w0[13]); FMA2(b1, h6y,  w1[13]);                           \
    FMA2(a0, h7x,  w0[14]); FMA2(b0, h7x,  w1[14]);                           \
    FMA2(a1, h7y,  w0[15]); FMA2(b1, h7y,  w1[15]);                           \
    FMA2(a0, h8x,  w0[16]); FMA2(b0, h8x,  w1[16]);                           \
    FMA2(a1, h8y,  w0[17]); FMA2(b1, h8y,  w1[17]);                           \
    FMA2(a0, h9x,  w0[18]); FMA2(b0, h9x,  w1[18]);                           \
    FMA2(a1, h9y,  w0[19]); FMA2(b1, h9y,  w1[19]);                           \
    FMA2(a0, h10x, w0[20]); FMA2(b0, h10x, w1[20]);                           \
    FMA2(a1, h10y, w0[21]); FMA2(b1, h10y, w1[21]);                           \
    FMA2(a0, h11x, w0[22]); FMA2(b0, h11x, w1[22]);                           \
    FMA2(a1, h11y, w0[23]); FMA2(b1, h11y, w1[23]);                           \
    FMA2(a0, hl, w0[24]);   FMA2(b0, hl, w1[24]);                             \
    ull s0, s1;                                                               \
    ADD2(s0, a0, a1);                                                         \
    ADD2(s1, b0, b1);                                                         \
    float lo0, up0, lo1, up1;                                                 \
    unpackf2(s0, lo0, up0);                                                   \
    unpackf2(s1, lo1, up1);                                                   \
    sts1i<(U + 1) * ROWB>(hag_l4, fmaxf(lo0 + up0, 0.f));                     \
    sts1i<(U + 1) * ROWB + 128>(hag_l4, fmaxf(lo1 + up1, 0.f));               \
    lds2i<(U + 1) * ROWB +  0>(P0x, P0y, hag);                                \
    lds2i<(U + 1) * ROWB + 16>(P1x, P1y, hag);                                \
    lds2i<(U + 1) * ROWB + 32>(P2x, P2y, hag);                                \
    lds2i<(U + 1) * ROWB + 48>(P3x, P3y, hag);                                \
} while (0)

__global__ __launch_bounds__(128, 1)
void rnn_kernel(const float* __restrict__ x,
                const float* __restrict__ W_ih,
                const float* __restrict__ W_hh,
                const float* __restrict__ b_ih,
                const float* __restrict__ b_hh,
                const float* __restrict__ W_out,
                const float* __restrict__ b_out,
                float* __restrict__ y)
{
    __shared__ __align__(16) float hist[4][CH + 1][HSTRIDE];   // 35,904 B
    __shared__ __align__(16) float xs[4][2][CH][4];            //  4,096 B
    __shared__ ull  wosh[3][25];
    __shared__ float bosh[3];

    const int tid  = threadIdx.x;
    const int warp = tid >> 5;
    const int lane = tid & 31;
    const int b = blockIdx.x * 4 + warp;

    if (tid < 75) {
        const int d = tid / 25, q = tid % 25;
        wosh[d][q] = packf2(W_out[d * HH + 2 * q], W_out[d * HH + 2 * q + 1]);
    }
    if (tid < 3) bosh[tid] = b_out[tid];

    const int j0 = lane;
    const int j1 = lane + 32;
    const bool j1v = (j1 < HH);

    ull w0[25], w1[25];
#pragma unroll
    for (int q = 0; q < 25; q++) {
        w0[q] = packf2(W_hh[j0 * HH + 2 * q], W_hh[j0 * HH + 2 * q + 1]);
        w1[q] = j1v ? packf2(W_hh[j1 * HH + 2 * q], W_hh[j1 * HH + 2 * q + 1]) : 0ull;
    }
    const float wi0a = W_ih[j0 * 3 + 0], wi0b = W_ih[j0 * 3 + 1], wi0c = W_ih[j0 * 3 + 2];
    const float bias0 = b_ih[j0] + b_hh[j0];
    const float wi1a = j1v ? W_ih[j1 * 3 + 0] : 0.f;
    const float wi1b = j1v ? W_ih[j1 * 3 + 1] : 0.f;
    const float wi1c = j1v ? W_ih[j1 * 3 + 2] : 0.f;
    const float bias1 = j1v ? (b_ih[j1] + b_hh[j1]) : 0.f;

    float* const hwarp = &hist[warp][0][0];
    const uint32_t hA_s = (uint32_t)__cvta_generic_to_shared(hwarp);
    const uint32_t xs_s = (uint32_t)__cvta_generic_to_shared(&xs[warp][0][0][0]);
    const uint32_t l4 = lane * 4;

    // h_{-1} = 0 in row 0 (cols 50..63 rewritten as 0 each step)
    sts1f(hA_s + l4, 0.f);
    sts1f(hA_s + l4 + 128, 0.f);

    const float* __restrict__ xb = x + (size_t)b * TT * 3;
    float* __restrict__ yb = y + (size_t)b * TT * 3;

    // stage x chunk 0: scatter [t][e] -> slot t*16 + e*4  (layout the loop reads)
#pragma unroll
    for (int e = 0; e < 3; e++) {
        const int gi = lane + e * 32;    // 0..95
        const uint32_t doff = (uint32_t)((gi / 3) * 16 + (gi % 3) * 4);
        CP_ASYNC4(xs_s + doff, xb + gi);
    }
    CP_COMMIT();
    CP_WAIT0();
    __syncthreads();   // wosh/bosh + staged x visibility (outside hot loop)

    // initial prefetch of row 0 vectors 0..3
    ull P0x, P0y, P1x, P1y, P2x, P2y, P3x, P3y;
    lds2i< 0>(P0x, P0y, hA_s);
    lds2i<16>(P1x, P1y, hA_s);
    lds2i<32>(P2x, P2y, hA_s);
    lds2i<48>(P3x, P3y, hA_s);

    int buf = 0;
    for (int base = 0; base < TT; base += CH) {
        const int cnt = min(CH, TT - base);     // 32 or 16, both %4 == 0

        // prefetch next chunk's x into the other buffer (scatter layout)
        if (base + CH < TT) {
            const int ncnt = min(CH, TT - base - CH);
            const uint32_t dbase = xs_s + (uint32_t)((buf ^ 1) * 512);
#pragma unroll
            for (int e = 0; e < 3; e++) {
                const int gi = lane + e * 32;
                if (gi < ncnt * 3) {
                    const uint32_t doff = (uint32_t)((gi / 3) * 16 + (gi % 3) * 4);
                    CP_ASYNC4(dbase + doff, xb + (size_t)(base + CH) * 3 + gi);
                }
            }
        }
        CP_COMMIT();

        uint32_t hag = hA_s;
        uint32_t hag_l4 = hA_s + l4;
        uint32_t xag = xs_s + (uint32_t)(buf * 512);

        for (int g = 0; g < cnt; g += 4) {
            STEP(0);
            STEP(1);
            STEP(2);
            STEP(3);
            hag += 4 * ROWB;
            hag_l4 += 4 * ROWB;
            xag += 64;
        }
        // after the loop: hag = row cnt; P holds row cnt vectors 0..3
        // carry row cnt -> row 0 (P already matches row 0's future content)
        sts1f(hA_s + l4,       lds1f(hag_l4));
        sts1f(hA_s + l4 + 128, lds1f(hag_l4 + 128));

        // ---- chunk projection: lane s owns timestep base+s (row s+1) ----
        if (lane < cnt) {
            const float* pr = hwarp + (lane + 1) * HSTRIDE;
            ull a0 = 0ull, c0 = 0ull, a1 = 0ull, c1 = 0ull, a2 = 0ull, c2 = 0ull;
#pragma unroll
            for (int p = 0; p < 12; p++) {
                const ulonglong2 hv = *reinterpret_cast<const ulonglong2*>(pr + 4 * p);
                FMA2(a0, hv.x, wosh[0][2 * p]); FMA2(c0, hv.y, wosh[0][2 * p + 1]);
                FMA2(a1, hv.x, wosh[1][2 * p]); FMA2(c1, hv.y, wosh[1][2 * p + 1]);
                FMA2(a2, hv.x, wosh[2][2 * p]); FMA2(c2, hv.y, wosh[2][2 * p + 1]);
            }
            const ull hl = *reinterpret_cast<const ull*>(pr + 48);
            FMA2(a0, hl, wosh[0][24]);
            FMA2(a1, hl, wosh[1][24]);
            FMA2(a2, hl, wosh[2][24]);

            ull s0, s1, s2;
            ADD2(s0, a0, c0); ADD2(s1, a1, c1); ADD2(s2, a2, c2);
            float p0l, p0h, p1l, p1h, p2l, p2h;
            unpackf2(s0, p0l, p0h);
            unpackf2(s1, p1l, p1h);
            unpackf2(s2, p2l, p2h);
            float* yo = yb + (size_t)(base + lane) * 3;
            yo[0] = p0l + p0h + bosh[0];
            yo[1] = p1l + p1h + bosh[1];
            yo[2] = p2l + p2h + bosh[2];
        }

        CP_WAIT0();
        __syncwarp();
        buf ^= 1;
    }
}

extern "C" void kernel_launch(void* const* d_in, const int* in_sizes, int n_in,
                              void* d_out, int out_size) {
    const float* x     = (const float*)d_in[0];
    const float* W_ih  = (const float*)d_in[1];
    const float* W_hh  = (const float*)d_in[2];
    const float* b_ih  = (const float*)d_in[3];
    const float* b_hh  = (const float*)d_in[4];
    const float* W_out = (const float*)d_in[5];
    const float* b_out = (const float*)d_in[6];
    float* y = (float*)d_out;

    rnn_kernel<<<BB / 4, 128>>>(x, W_ih, W_hh, b_ih, b_hh, W_out, b_out, y);
}

// round 14
// speedup vs baseline: 2.0371x; 1.0089x over previous
#include <cuda_runtime.h>
#include <cstdint>

#define BB 512
#define TT 2000
#define HH 50
#define CH 32
#define HSTRIDE 68     // floats per hist row, 16B-aligned rows

typedef unsigned long long ull;

__device__ __forceinline__ ull packf2(float a, float b) {
    ull r;
    asm("mov.b64 %0, {%1, %2};" : "=l"(r) : "f"(a), "f"(b));
    return r;
}
__device__ __forceinline__ void unpackf2(ull v, float& lo, float& hi) {
    asm("mov.b64 {%0, %1}, %2;" : "=f"(lo), "=f"(hi) : "l"(v));
}
#define FMA2(acc, a, b) \
    asm("fma.rn.f32x2 %0, %1, %2, %0;" : "+l"(acc) : "l"(a), "l"(b))
#define ADD2(dst, a, b) \
    asm("add.rn.f32x2 %0, %1, %2;" : "=l"(dst) : "l"(a), "l"(b))
#define CP_ASYNC16(dst_u32, src) \
    asm volatile("cp.async.ca.shared.global [%0], [%1], 16;" :: "r"(dst_u32), "l"(src))
#define CP_COMMIT() asm volatile("cp.async.commit_group;")
#define CP_WAIT0()  asm volatile("cp.async.wait_group 0;")

__global__ __launch_bounds__(128, 1)
void rnn_kernel(const float* __restrict__ x,
                const float* __restrict__ W_ih,
                const float* __restrict__ W_hh,
                const float* __restrict__ b_ih,
                const float* __restrict__ b_hh,
                const float* __restrict__ W_out,
                const float* __restrict__ b_out,
                float* __restrict__ y)
{
    // per-warp 33-row history: step s reads row s, writes row s+1; NO syncs.
    __shared__ __align__(16) float hist[4][CH + 1][HSTRIDE];   // 35,904 B
    __shared__ __align__(16) float xs[4][2][3 * CH];           //  3,072 B
    __shared__ ull  wosh[3][25];
    __shared__ float bosh[3];

    const int tid  = threadIdx.x;
    const int warp = tid >> 5;
    const int lane = tid & 31;
    const int b = blockIdx.x * 4 + warp;

    if (tid < 75) {
        const int d = tid / 25, q = tid % 25;
        wosh[d][q] = packf2(W_out[d * HH + 2 * q], W_out[d * HH + 2 * q + 1]);
    }
    if (tid < 3) bosh[tid] = b_out[tid];

    const int j0 = lane;            // < 50 always
    const int j1 = lane + 32;       // real only for lanes 0..17
    const bool j1v = (j1 < HH);

    // per-lane packed W_hh rows (25 k-pairs each); zero rows for padded j1
    ull w0[25], w1[25];
#pragma unroll
    for (int q = 0; q < 25; q++) {
        w0[q] = packf2(W_hh[j0 * HH + 2 * q], W_hh[j0 * HH + 2 * q + 1]);
        w1[q] = j1v ? packf2(W_hh[j1 * HH + 2 * q], W_hh[j1 * HH + 2 * q + 1]) : 0ull;
    }
    const float wi0a = W_ih[j0 * 3 + 0], wi0b = W_ih[j0 * 3 + 1], wi0c = W_ih[j0 * 3 + 2];
    const float bias0 = b_ih[j0] + b_hh[j0];
    const float wi1a = j1v ? W_ih[j1 * 3 + 0] : 0.f;
    const float wi1b = j1v ? W_ih[j1 * 3 + 1] : 0.f;
    const float wi1c = j1v ? W_ih[j1 * 3 + 2] : 0.f;
    const float bias1 = j1v ? (b_ih[j1] + b_hh[j1]) : 0.f;

    float* const hwarp = &hist[warp][0][0];
    hwarp[lane] = 0.f;           // h_{-1} = 0 (cols 50..63 rewritten as 0 each step)
    hwarp[lane + 32] = 0.f;

    const float* __restrict__ xb = x + (size_t)b * TT * 3;
    float* __restrict__ yb = y + (size_t)b * TT * 3;

    // stage x chunk 0 via cp.async (96 floats = lanes 0..23 x 16B)
    const uint32_t xs_base0 = (uint32_t)__cvta_generic_to_shared(&xs[warp][0][0]);
    const uint32_t xs_base1 = (uint32_t)__cvta_generic_to_shared(&xs[warp][1][0]);
    if (lane < 24) CP_ASYNC16(xs_base0 + lane * 16, xb + lane * 4);
    CP_COMMIT();
    CP_WAIT0();
    __syncthreads();     // wosh/bosh + x chunk 0 visibility (outside hot loop)

    int buf = 0;
    for (int base = 0; base < TT; base += CH) {
        const int cnt = min(CH, TT - base);     // 32 or 16, both %4 == 0

        // prefetch next chunk's x straight into the other smem buffer
        {
            const int ncnt = min(CH, TT - base - CH);
            if (base + CH < TT && lane * 16 < ncnt * 12) {
                const uint32_t dst = (buf ? xs_base0 : xs_base1) + lane * 16;
                CP_ASYNC16(dst, xb + (size_t)(base + CH) * 3 + lane * 4);
            }
            CP_COMMIT();
        }

        const float* __restrict__ xp = &xs[warp][buf][0];

        // ---- recurrence: warp-private smem, no syncs, 3 chains per j ----
        for (int g = 0; g < cnt; g += 4) {
#pragma unroll
            for (int u = 0; u < 4; u++) {
                const int s = g + u;
                const float x0 = xp[3 * s + 0];
                const float x1 = xp[3 * s + 1];
                const float x2 = xp[3 * s + 2];
                const float xh0 = fmaf(x2, wi0c, fmaf(x1, wi0b, fmaf(x0, wi0a, bias0)));
                const float xh1 = fmaf(x2, wi1c, fmaf(x1, wi1b, fmaf(x0, wi1a, bias1)));

                const float* hr = hwarp + s * HSTRIDE;
                // 3 accumulator chains per j: depths 5/4/4 instead of 13
                ull a0 = packf2(xh0, 0.f), a1 = 0ull, a2 = 0ull;
                ull b0 = packf2(xh1, 0.f), b1 = 0ull, b2 = 0ull;
#pragma unroll
                for (int p = 0; p < 12; p++) {
                    const ulonglong2 hv = *reinterpret_cast<const ulonglong2*>(hr + 4 * p);
                    if (p % 3 == 0) {
                        FMA2(a0, hv.x, w0[2 * p]);
                        FMA2(b0, hv.x, w1[2 * p]);
                        FMA2(a1, hv.y, w0[2 * p + 1]);
                        FMA2(b1, hv.y, w1[2 * p + 1]);
                    } else if (p % 3 == 1) {
                        FMA2(a1, hv.x, w0[2 * p]);
                        FMA2(b1, hv.x, w1[2 * p]);
                        FMA2(a2, hv.y, w0[2 * p + 1]);
                        FMA2(b2, hv.y, w1[2 * p + 1]);
                    } else {
                        FMA2(a2, hv.x, w0[2 * p]);
                        FMA2(b2, hv.x, w1[2 * p]);
                        FMA2(a0, hv.y, w0[2 * p + 1]);
                        FMA2(b0, hv.y, w1[2 * p + 1]);
                    }
                }
                const ull hl = *reinterpret_cast<const ull*>(hr + 48);  // h[48..49]
                FMA2(a0, hl, w0[24]);
                FMA2(b0, hl, w1[24]);

                // 2-level tail tree
                ull t0, t1, s0, s1;
                ADD2(t0, a1, a2);
                ADD2(t1, b1, b2);
                ADD2(s0, a0, t0);
                ADD2(s1, b0, t1);
                float l0, u0, l1, u1;
                unpackf2(s0, l0, u0);
                unpackf2(s1, l1, u1);
                const float h0 = fmaxf(l0 + u0, 0.f);
                const float h1 = fmaxf(l1 + u1, 0.f);   // exactly 0 for padded j1

                float* hw = hwarp + (s + 1) * HSTRIDE;
                hw[lane] = h0;
                hw[lane + 32] = h1;
            }
        }

        // carry h_{last} into row 0 for next chunk (same-warp in-order smem)
        hwarp[lane] = hwarp[cnt * HSTRIDE + lane];
        hwarp[lane + 32] = hwarp[cnt * HSTRIDE + lane + 32];

        // ---- chunk projection: lane s owns timestep base+s (row s+1) ----
        if (lane < cnt) {
            const float* pr = hwarp + (lane + 1) * HSTRIDE;
            ull a0 = 0ull, c0 = 0ull, a1 = 0ull, c1 = 0ull, a2 = 0ull, c2 = 0ull;
#pragma unroll
            for (int p = 0; p < 12; p++) {
                const ulonglong2 hv = *reinterpret_cast<const ulonglong2*>(pr + 4 * p);
                FMA2(a0, hv.x, wosh[0][2 * p]); FMA2(c0, hv.y, wosh[0][2 * p + 1]);
                FMA2(a1, hv.x, wosh[1][2 * p]); FMA2(c1, hv.y, wosh[1][2 * p + 1]);
                FMA2(a2, hv.x, wosh[2][2 * p]); FMA2(c2, hv.y, wosh[2][2 * p + 1]);
            }
            const ull hl = *reinterpret_cast<const ull*>(pr + 48);
            FMA2(a0, hl, wosh[0][24]);
            FMA2(a1, hl, wosh[1][24]);
            FMA2(a2, hl, wosh[2][24]);

            ull s0, s1, s2;
            ADD2(s0, a0, c0); ADD2(s1, a1, c1); ADD2(s2, a2, c2);
            float p0l, p0h, p1l, p1h, p2l, p2h;
            unpackf2(s0, p0l, p0h);
            unpackf2(s1, p1l, p1h);
            unpackf2(s2, p2l, p2h);
            float* yo = yb + (size_t)(base + lane) * 3;
            yo[0] = p0l + p0h + bosh[0];
            yo[1] = p1l + p1h + bosh[1];
            yo[2] = p2l + p2h + bosh[2];
        }

        // next chunk's x must be in smem and warp-visible
        CP_WAIT0();
        __syncwarp();
        buf ^= 1;
    }
}

extern "C" void kernel_launch(void* const* d_in, const int* in_sizes, int n_in,
                              void* d_out, int out_size) {
    const float* x     = (const float*)d_in[0];
    const float* W_ih  = (const float*)d_in[1];
    const float* W_hh  = (const float*)d_in[2];
    const float* b_ih  = (const float*)d_in[3];
    const float* b_hh  = (const float*)d_in[4];
    const float* W_out = (const float*)d_in[5];
    const float* b_out = (const float*)d_in[6];
    float* y = (float*)d_out;

    rnn_kernel<<<BB / 4, 128>>>(x, W_ih, W_hh, b_ih, b_hh, W_out, b_out, y);
}